// round 15
// baseline (speedup 1.0000x reference)
#include <cuda_runtime.h>
#include <cuda_bf16.h>
#include <cstdint>
#include <cstddef>

// Problem constants
#define Bc  4
#define Sc  2048
#define Dc  1024
#define Hc  16
#define DKc 64
#define BHc (Bc*Hc)                     // 64
#define SCALEc 0.125f                   // DK^-0.5
#define EPSc 1e-6f

constexpr size_t XE = (size_t)Bc*Sc*Dc;       // 8,388,608
constexpr size_t AE = (size_t)Bc*Hc*Sc*Sc;    // 268,435,456

// ---------------- scratch (device globals: allocation-free) ----------------
__device__ float g_q3[XE];        // tf32-rounded copies of q,k,v
__device__ float g_k3[XE];
__device__ float g_v3[XE];
__device__ float g_qh[XE];        // [B,H,S,DK] tf32-pure (q scaled by 1/8)
__device__ float g_kh[XE];
__device__ float g_vh[XE];
__device__ float g_ao[XE];        // attn@V [B,S,H*DK], tf32-pure
__device__ float g_x[XE];         // pre-LN activations (fp32)
__device__ float g_wt_q[Dc*Dc];   // Wq^T  [N,K] K-major, tf32-pure
__device__ float g_wt_fc[Dc*Dc];  // Wfc^T [N,K] K-major, tf32-pure
__device__ float g_psum[(size_t)BHc*16*Sc];   // partial row sums of exp
__device__ float g_rinv[(size_t)BHc*Sc];      // 1 / row sum
__device__ float g_attn_fb[AE];   // fallback if harness only wants x

// ============================================================================
// PTX helpers (all sm_80-or-earlier: legal on compute_103 target)
// ============================================================================
__device__ __forceinline__ float f2tf_f(float x) {
    uint32_t r;
    asm("cvt.rna.tf32.f32 %0, %1;" : "=r"(r) : "f"(x));
    return __uint_as_float(r);
}
// D += A(16x8) @ B(8x8);  fp32 accum, operands are tf32 bit patterns
__device__ __forceinline__ void mma8(float* d, const uint32_t* a, const uint32_t* b) {
    asm volatile(
        "mma.sync.aligned.m16n8k8.row.col.f32.tf32.tf32.f32 "
        "{%0,%1,%2,%3}, {%4,%5,%6,%7}, {%8,%9}, {%0,%1,%2,%3};"
        : "+f"(d[0]), "+f"(d[1]), "+f"(d[2]), "+f"(d[3])
        : "r"(a[0]), "r"(a[1]), "r"(a[2]), "r"(a[3]), "r"(b[0]), "r"(b[1]));
}
__device__ __forceinline__ uint32_t smem_u32p(const void* p) {
    uint32_t a;
    asm("{ .reg .u64 t; cvta.to.shared.u64 t, %1; cvt.u32.u64 %0, t; }"
        : "=r"(a) : "l"(p));
    return a;
}
#define CP_ASYNC16(dst_u32, src_gen) \
    asm volatile("cp.async.cg.shared.global [%0], [%1], 16;" \
                 :: "r"(dst_u32), "l"(src_gen) : "memory")
#define CP_COMMIT() asm volatile("cp.async.commit_group;" ::: "memory")
#define CP_WAIT(n)  asm volatile("cp.async.wait_group %0;" :: "n"(n) : "memory")
#define LDMX4(r0, r1, r2, r3, addr) \
    asm volatile("ldmatrix.sync.aligned.m8n8.x4.shared.b16 {%0,%1,%2,%3}, [%4];" \
                 : "=r"(r0), "=r"(r1), "=r"(r2), "=r"(r3) : "r"(addr))

// ============================================================================
// tf32-ize an array (float4)
// ============================================================================
__global__ __launch_bounds__(256) void tf32ize(
    const float* __restrict__ src, float* __restrict__ dst, int n4)
{
    const int idx = blockIdx.x * 256 + threadIdx.x;
    if (idx < n4) {
        float4 v = ((const float4*)src)[idx];
        v.x = f2tf_f(v.x); v.y = f2tf_f(v.y);
        v.z = f2tf_f(v.z); v.w = f2tf_f(v.w);
        ((float4*)dst)[idx] = v;
    }
}

// ============================================================================
// Transpose 1024x1024 + tf32-ize: Wt[n,k] = tf32(W[k,n])
// ============================================================================
__global__ __launch_bounds__(256) void transpose1024(
    const float* __restrict__ W, float* __restrict__ Wt)
{
    __shared__ float tile[32][33];
    const int x = blockIdx.x * 32 + threadIdx.x;
    const int y = blockIdx.y * 32 + threadIdx.y;
    #pragma unroll
    for (int j = 0; j < 32; j += 8)
        tile[threadIdx.y + j][threadIdx.x] = W[(size_t)(y + j) * Dc + x];
    __syncthreads();
    const int xo = blockIdx.y * 32 + threadIdx.x;
    const int yo = blockIdx.x * 32 + threadIdx.y;
    #pragma unroll
    for (int j = 0; j < 32; j += 8)
        Wt[(size_t)(yo + j) * Dc + xo] = f2tf_f(tile[threadIdx.x][threadIdx.y + j]);
}

// ============================================================================
// Dense GEMM (tf32 mma + ldmatrix + cp.async 3-stage):
// C[M,1024]=A[M,1024]@Bt^T (+bias, *outScale, +resid). A,Bt tf32-pure.
// 128x128 CTA, 8 warps (2x4), warp tile 64x32.
// ============================================================================
#define GSTRIDE 20
#define GSTAGE  2560                       // 128*20 floats
#define GEMM_SMEM (3 * GSTAGE * 2 * 4)     // 61440 B

__global__ __launch_bounds__(256) void gemm_mma(
    const float* __restrict__ A, const float* __restrict__ Bt,
    const float* __restrict__ bias, const float* __restrict__ resid,
    float* __restrict__ C, int headLayout, float outScale)
{
    extern __shared__ float smf[];
    float* Asf = smf;                  // [3][128][20]
    float* Bsf = smf + 3 * GSTAGE;     // [3][128][20]
    const uint32_t asb = smem_u32p(Asf);
    const uint32_t bsb = smem_u32p(Bsf);

    const int tid  = threadIdx.x;
    const int lane = tid & 31;
    const int warp = tid >> 5;
    const int g = lane >> 2, t = lane & 3;
    const int wm = (warp >> 2) * 64;
    const int wn = (warp & 3) * 32;
    const int mBase = blockIdx.y * 128;
    const int nBase = blockIdx.x * 128;

    const int i8 = lane & 7, qd = lane >> 3;
    const int a_off = (wm + i8 + (qd & 1) * 8) * GSTRIDE + (qd >> 1) * 4;
    const int b_off = (wn + i8 + (qd >> 1) * 8) * GSTRIDE + (qd & 1) * 4;

    const int lrow = tid >> 1;
    const int lhalf = (tid & 1) * 8;
    const float* Ap = A  + (size_t)(mBase + lrow) * Dc + lhalf;
    const float* Bp = Bt + (size_t)(nBase + lrow) * Dc + lhalf;
    const uint32_t adst = (uint32_t)((lrow * GSTRIDE + lhalf) * 4);

    float acc[4][4][4];
    #pragma unroll
    for (int i = 0; i < 4; i++)
        #pragma unroll
        for (int j = 0; j < 4; j++)
            #pragma unroll
            for (int r = 0; r < 4; r++) acc[i][j][r] = 0.f;

    #pragma unroll
    for (int s = 0; s < 2; s++) {
        const uint32_t ad = asb + s * (GSTAGE * 4) + adst;
        const uint32_t bd = bsb + s * (GSTAGE * 4) + adst;
        CP_ASYNC16(ad,      Ap + s * 16);
        CP_ASYNC16(ad + 16, Ap + s * 16 + 4);
        CP_ASYNC16(bd,      Bp + s * 16);
        CP_ASYNC16(bd + 16, Bp + s * 16 + 4);
        CP_COMMIT();
    }

    #pragma unroll 1
    for (int kt = 0; kt < 64; kt++) {
        CP_WAIT(1);
        __syncthreads();
        const int cur = kt % 3;
        const uint32_t ab = asb + cur * (GSTAGE * 4);
        const uint32_t bb = bsb + cur * (GSTAGE * 4);
        #pragma unroll
        for (int ks = 0; ks < 2; ks++) {
            const int k0 = ks * 8;
            uint32_t afr[4][4], bfr[4][2];
            #pragma unroll
            for (int mt = 0; mt < 4; mt++)
                LDMX4(afr[mt][0], afr[mt][1], afr[mt][2], afr[mt][3],
                      ab + (uint32_t)((a_off + mt * 16 * GSTRIDE + k0) << 2));
            #pragma unroll
            for (int p = 0; p < 2; p++)
                LDMX4(bfr[2*p][0], bfr[2*p][1], bfr[2*p+1][0], bfr[2*p+1][1],
                      bb + (uint32_t)((b_off + p * 16 * GSTRIDE + k0) << 2));
            #pragma unroll
            for (int mt = 0; mt < 4; mt++)
                #pragma unroll
                for (int nt = 0; nt < 4; nt++)
                    mma8(acc[mt][nt], afr[mt], bfr[nt]);
        }
        if (kt + 2 < 64) {
            const int nst = (kt + 2) % 3;
            const uint32_t ad = asb + nst * (GSTAGE * 4) + adst;
            const uint32_t bd = bsb + nst * (GSTAGE * 4) + adst;
            CP_ASYNC16(ad,      Ap + (kt + 2) * 16);
            CP_ASYNC16(ad + 16, Ap + (kt + 2) * 16 + 4);
            CP_ASYNC16(bd,      Bp + (kt + 2) * 16);
            CP_ASYNC16(bd + 16, Bp + (kt + 2) * 16 + 4);
        }
        CP_COMMIT();
    }

    #pragma unroll
    for (int mt = 0; mt < 4; mt++) {
        #pragma unroll
        for (int nt = 0; nt < 4; nt++) {
            const int col = nBase + wn + nt * 8 + t * 2;
            #pragma unroll
            for (int h2 = 0; h2 < 2; h2++) {
                const int row = mBase + wm + mt * 16 + g + h2 * 8;
                float2 v;
                v.x = (acc[mt][nt][h2 * 2 + 0] + bias[col    ]) * outScale;
                v.y = (acc[mt][nt][h2 * 2 + 1] + bias[col + 1]) * outScale;
                if (resid) {
                    const float2 r = *(const float2*)(resid + (size_t)row * Dc + col);
                    v.x += r.x; v.y += r.y;
                }
                if (headLayout) {
                    v.x = f2tf_f(v.x); v.y = f2tf_f(v.y);
                    const int b = row >> 11, sI = row & 2047;
                    const int h = col >> 6, dk = col & 63;
                    *(float2*)(C + (((size_t)(b * Hc + h)) * Sc + sI) * DKc + dk) = v;
                } else {
                    *(float2*)(C + (size_t)row * Dc + col) = v;
                }
            }
        }
    }
}

// ============================================================================
// Scores + exp + partial row sums (softmax fused, no max: scores are O(2.5)):
// per (b,h) attn[r,c] = exp(qh[r]·kh[c])   (scale pre-folded into qh)
// partial sums per (bh, nblock, row) -> g_psum (deterministic, no atomics).
// ============================================================================
#define SCORES_SMEM (4 * GSTAGE * 2 * 4)   // 81920 B

__global__ __launch_bounds__(256) void scores_mma(
    const float* __restrict__ qh, const float* __restrict__ kh,
    float* __restrict__ attn_out)
{
    float* attn = attn_out ? attn_out : g_attn_fb;
    extern __shared__ float smf[];
    float* Asf = smf;
    float* Bsf = smf + 4 * GSTAGE;
    const uint32_t asb = smem_u32p(Asf);
    const uint32_t bsb = smem_u32p(Bsf);

    const int tid  = threadIdx.x;
    const int lane = tid & 31;
    const int warp = tid >> 5;
    const int g = lane >> 2, t = lane & 3;
    const int wm = (warp >> 2) * 64;
    const int wn = (warp & 3) * 32;
    const int bh = blockIdx.z;
    const int mBase = blockIdx.y * 128;
    const int nBase = blockIdx.x * 128;

    const int i8 = lane & 7, qd = lane >> 3;
    const int a_off = (wm + i8 + (qd & 1) * 8) * GSTRIDE + (qd >> 1) * 4;
    const int b_off = (wn + i8 + (qd >> 1) * 8) * GSTRIDE + (qd & 1) * 4;

    const int lrow = tid >> 1;
    const int lhalf = (tid & 1) * 8;
    const float* Ap = qh + (size_t)bh * Sc * DKc + (size_t)(mBase + lrow) * DKc + lhalf;
    const float* Bp = kh + (size_t)bh * Sc * DKc + (size_t)(nBase + lrow) * DKc + lhalf;
    float* Cp = attn + (size_t)bh * Sc * Sc;
    const uint32_t adst = (uint32_t)((lrow * GSTRIDE + lhalf) * 4);

    #pragma unroll
    for (int s = 0; s < 4; s++) {
        const uint32_t ad = asb + s * (GSTAGE * 4) + adst;
        const uint32_t bd = bsb + s * (GSTAGE * 4) + adst;
        CP_ASYNC16(ad,      Ap + s * 16);
        CP_ASYNC16(ad + 16, Ap + s * 16 + 4);
        CP_ASYNC16(bd,      Bp + s * 16);
        CP_ASYNC16(bd + 16, Bp + s * 16 + 4);
    }
    CP_COMMIT();

    float acc[4][4][4];
    #pragma unroll
    for (int i = 0; i < 4; i++)
        #pragma unroll
        for (int j = 0; j < 4; j++)
            #pragma unroll
            for (int r = 0; r < 4; r++) acc[i][j][r] = 0.f;

    CP_WAIT(0);
    __syncthreads();

    #pragma unroll
    for (int kt = 0; kt < 4; kt++) {
        const uint32_t ab = asb + kt * (GSTAGE * 4);
        const uint32_t bb = bsb + kt * (GSTAGE * 4);
        #pragma unroll
        for (int ks = 0; ks < 2; ks++) {
            const int k0 = ks * 8;
            uint32_t afr[4][4], bfr[4][2];
            #pragma unroll
            for (int mt = 0; mt < 4; mt++)
                LDMX4(afr[mt][0], afr[mt][1], afr[mt][2], afr[mt][3],
                      ab + (uint32_t)((a_off + mt * 16 * GSTRIDE + k0) << 2));
            #pragma unroll
            for (int p = 0; p < 2; p++)
                LDMX4(bfr[2*p][0], bfr[2*p][1], bfr[2*p+1][0], bfr[2*p+1][1],
                      bb + (uint32_t)((b_off + p * 16 * GSTRIDE + k0) << 2));
            #pragma unroll
            for (int mt = 0; mt < 4; mt++)
                #pragma unroll
                for (int nt = 0; nt < 4; nt++)
                    mma8(acc[mt][nt], afr[mt], bfr[nt]);
        }
    }

    // epilogue: exp + store + per-row partial sums
    float rs[4][2];
    #pragma unroll
    for (int mt = 0; mt < 4; mt++) { rs[mt][0] = 0.f; rs[mt][1] = 0.f; }

    #pragma unroll
    for (int mt = 0; mt < 4; mt++) {
        #pragma unroll
        for (int nt = 0; nt < 4; nt++) {
            const int col = nBase + wn + nt * 8 + t * 2;
            #pragma unroll
            for (int h2 = 0; h2 < 2; h2++) {
                const int row = mBase + wm + mt * 16 + g + h2 * 8;
                float2 v;
                v.x = __expf(acc[mt][nt][h2 * 2 + 0]);
                v.y = __expf(acc[mt][nt][h2 * 2 + 1]);
                rs[mt][h2] += v.x + v.y;
                *(float2*)(Cp + (size_t)row * Sc + col) = v;
            }
        }
    }

    __syncthreads();          // tile reads done; reuse Asf as psum buffer
    float* psum = Asf;        // [4][128]
    #pragma unroll
    for (int mt = 0; mt < 4; mt++) {
        #pragma unroll
        for (int h2 = 0; h2 < 2; h2++) {
            float s = rs[mt][h2];
            s += __shfl_xor_sync(0xFFFFFFFFu, s, 1);
            s += __shfl_xor_sync(0xFFFFFFFFu, s, 2);
            if (t == 0)
                psum[(warp & 3) * 128 + wm + mt * 16 + h2 * 8 + g] = s;
        }
    }
    __syncthreads();
    if (tid < 128) {
        const float tot = psum[tid] + psum[128 + tid] + psum[256 + tid] + psum[384 + tid];
        g_psum[(((size_t)bh * 16 + blockIdx.x) << 11) + mBase + tid] = tot;
    }
}

// ============================================================================
// Row inverse sums: g_rinv[bh*S + row] = 1 / sum_j g_psum[bh][j][row]
// ============================================================================
__global__ __launch_bounds__(256) void rowinv_k()
{
    const int r = blockIdx.x * 256 + threadIdx.x;    // 0 .. BH*S-1
    const int bh = r >> 11, row = r & 2047;
    float s = 0.f;
    #pragma unroll
    for (int j = 0; j < 16; j++)
        s += g_psum[(((size_t)bh * 16 + j) << 11) + row];
    g_rinv[r] = 1.f / s;
}

// ============================================================================
// attn @ V (unnormalized exp in, scaling fused):
// ao = diag(rinv) * (E @ V);  also writes normalized attn back in-place.
// per (b,h) [2048,2048] @ [2048,64]. 128x64 CTA, 8 warps (4x2), 4-stage.
// ============================================================================
#define VSTRIDE 72
#define VSTAGE  (16 * VSTRIDE)             // 1152 floats
#define AV_SMEM ((4 * GSTAGE + 4 * VSTAGE + 128) * 4)   // 59904 B

__global__ __launch_bounds__(256) void av_mma(
    float* __restrict__ attn_out, const float* __restrict__ vh,
    float* __restrict__ ao)
{
    float* attn = attn_out ? attn_out : g_attn_fb;
    extern __shared__ float smf[];
    float* Asf = smf;                    // [4][128][20]
    float* Vsf = smf + 4 * GSTAGE;       // [4][16][72]
    float* sinv = smf + 4 * GSTAGE + 4 * VSTAGE;   // [128]
    const uint32_t asb = smem_u32p(Asf);
    const uint32_t vsb = smem_u32p(Vsf);

    const int tid  = threadIdx.x;
    const int lane = tid & 31;
    const int warp = tid >> 5;
    const int g = lane >> 2, t = lane & 3;
    const int wm = (warp >> 1) * 32;
    const int wn = (warp & 1) * 32;
    const int bh = blockIdx.y;
    const int mBase = blockIdx.x * 128;

    const int i8 = lane & 7, qd = lane >> 3;
    const int a_off = (wm + i8 + (qd & 1) * 8) * GSTRIDE + (qd >> 1) * 4;

    const int lrow = tid >> 1;
    const int lhalf = (tid & 1) * 8;
    const int vrow = tid >> 4;
    const int vcol = (tid & 15) * 4;
    float* Ag = attn + (size_t)bh * Sc * Sc + (size_t)(mBase + lrow) * Sc + lhalf;
    const float* Vp = vh + (size_t)bh * Sc * DKc;
    const uint32_t adst = (uint32_t)((lrow * GSTRIDE + lhalf) * 4);
    const uint32_t vdst = (uint32_t)((vrow * VSTRIDE + vcol) * 4);

    if (tid < 128)
        sinv[tid] = g_rinv[(size_t)bh * Sc + mBase + tid];

    float acc[2][4][4];
    #pragma unroll
    for (int i = 0; i < 2; i++)
        #pragma unroll
        for (int j = 0; j < 4; j++)
            #pragma unroll
            for (int r = 0; r < 4; r++) acc[i][j][r] = 0.f;

    #pragma unroll
    for (int s = 0; s < 3; s++) {
        const uint32_t ad = asb + s * (GSTAGE * 4) + adst;
        CP_ASYNC16(ad,      Ag + s * 16);
        CP_ASYNC16(ad + 16, Ag + s * 16 + 4);
        CP_ASYNC16(vsb + s * (VSTAGE * 4) + vdst,
                   Vp + (size_t)(s * 16 + vrow) * DKc + vcol);
        CP_COMMIT();
    }

    float wrow_inv = 0.f;    // set after first sync (sinv visible then)

    #pragma unroll 1
    for (int kt = 0; kt < 128; kt++) {
        CP_WAIT(2);
        __syncthreads();
        if (kt == 0) wrow_inv = sinv[lrow];
        const int cur = kt & 3;
        const uint32_t ab = asb + cur * (GSTAGE * 4);
        const float* Af = Asf + cur * GSTAGE;
        const float* Vf = Vsf + cur * VSTAGE;

        // normalized attn write-back for this stage (cols kt*16 + lhalf..+8)
        {
            float4 w0 = *(const float4*)(Af + lrow * GSTRIDE + lhalf);
            float4 w1 = *(const float4*)(Af + lrow * GSTRIDE + lhalf + 4);
            w0.x *= wrow_inv; w0.y *= wrow_inv; w0.z *= wrow_inv; w0.w *= wrow_inv;
            w1.x *= wrow_inv; w1.y *= wrow_inv; w1.z *= wrow_inv; w1.w *= wrow_inv;
            *(float4*)(Ag + kt * 16)     = w0;
            *(float4*)(Ag + kt * 16 + 4) = w1;
        }

        #pragma unroll
        for (int ks = 0; ks < 2; ks++) {
            const int k0 = ks * 8;
            uint32_t afr[2][4], bfr[4][2];
            #pragma unroll
            for (int mt = 0; mt < 2; mt++)
                LDMX4(afr[mt][0], afr[mt][1], afr[mt][2], afr[mt][3],
                      ab + (uint32_t)((a_off + mt * 16 * GSTRIDE + k0) << 2));
            #pragma unroll
            for (int nt = 0; nt < 4; nt++) {
                const int c = wn + nt * 8 + g;
                bfr[nt][0] = __float_as_uint(Vf[(k0 + t    ) * VSTRIDE + c]);
                bfr[nt][1] = __float_as_uint(Vf[(k0 + t + 4) * VSTRIDE + c]);
            }
            #pragma unroll
            for (int mt = 0; mt < 2; mt++)
                #pragma unroll
                for (int nt = 0; nt < 4; nt++)
                    mma8(acc[mt][nt], afr[mt], bfr[nt]);
        }
        if (kt + 3 < 128) {
            const int nst = (kt + 3) & 3;
            const uint32_t ad = asb + nst * (GSTAGE * 4) + adst;
            CP_ASYNC16(ad,      Ag + (kt + 3) * 16);
            CP_ASYNC16(ad + 16, Ag + (kt + 3) * 16 + 4);
            CP_ASYNC16(vsb + nst * (VSTAGE * 4) + vdst,
                       Vp + (size_t)((kt + 3) * 16 + vrow) * DKc + vcol);
        }
        CP_COMMIT();
    }

    const int b = bh >> 4, h = bh & 15;
    #pragma unroll
    for (int mt = 0; mt < 2; mt++) {
        #pragma unroll
        for (int nt = 0; nt < 4; nt++) {
            const int col = wn + nt * 8 + t * 2;
            #pragma unroll
            for (int h2 = 0; h2 < 2; h2++) {
                const int lr = wm + mt * 16 + g + h2 * 8;
                const float inv = sinv[lr];
                const int row = mBase + lr;
                float2 v = { f2tf_f(acc[mt][nt][h2 * 2 + 0] * inv),
                             f2tf_f(acc[mt][nt][h2 * 2 + 1] * inv) };
                *(float2*)(ao + ((size_t)(b * Sc + row)) * Dc + h * DKc + col) = v;
            }
        }
    }
}

// ============================================================================
// LayerNorm over D=1024.
// ============================================================================
__global__ __launch_bounds__(256) void ln_k(
    const float* __restrict__ x, const float* __restrict__ gamma,
    const float* __restrict__ beta, float* __restrict__ out)
{
    __shared__ float r1[256];
    __shared__ float r2[256];
    const int t = threadIdx.x;
    const float* p = x + (size_t)blockIdx.x * Dc;

    float v[4];
    float s = 0.f, sq = 0.f;
    #pragma unroll
    for (int i = 0; i < 4; i++) {
        v[i] = p[t + i*256];
        s += v[i]; sq += v[i]*v[i];
    }
    r1[t] = s; r2[t] = sq; __syncthreads();
    for (int w = 128; w > 0; w >>= 1) {
        if (t < w) { r1[t] += r1[t+w]; r2[t] += r2[t+w]; }
        __syncthreads();
    }
    const float mu  = r1[0] * (1.f/Dc);
    const float var = r2[0] * (1.f/Dc) - mu*mu;
    const float inv = rsqrtf(var + EPSc);
    float* o = out + (size_t)blockIdx.x * Dc;
    #pragma unroll
    for (int i = 0; i < 4; i++) {
        const int c = t + i*256;
        o[c] = (v[i] - mu) * inv * gamma[c] + beta[c];
    }
}

// ============================================================================
// Launch
// ============================================================================
extern "C" void kernel_launch(void* const* d_in, const int* in_sizes, int n_in,
                              void* d_out, int out_size)
{
    const float* q     = (const float*)d_in[0];
    const float* k     = (const float*)d_in[1];
    const float* v     = (const float*)d_in[2];
    const float* Wq    = (const float*)d_in[3];
    const float* bq    = (const float*)d_in[4];
    const float* Wfc   = (const float*)d_in[5];
    const float* bfc   = (const float*)d_in[6];
    const float* gamma = (const float*)d_in[7];
    const float* beta  = (const float*)d_in[8];

    float* out = (float*)d_out;
    float* attn_region = ((size_t)out_size >= XE + AE) ? (out + XE) : nullptr;

    float *q3, *k3, *v3, *qh, *kh, *vh, *ao, *xb, *wtq, *wtfc;
    cudaGetSymbolAddress((void**)&q3,   g_q3);
    cudaGetSymbolAddress((void**)&k3,   g_k3);
    cudaGetSymbolAddress((void**)&v3,   g_v3);
    cudaGetSymbolAddress((void**)&qh,   g_qh);
    cudaGetSymbolAddress((void**)&kh,   g_kh);
    cudaGetSymbolAddress((void**)&vh,   g_vh);
    cudaGetSymbolAddress((void**)&ao,   g_ao);
    cudaGetSymbolAddress((void**)&xb,   g_x);
    cudaGetSymbolAddress((void**)&wtq,  g_wt_q);
    cudaGetSymbolAddress((void**)&wtfc, g_wt_fc);

    cudaFuncSetAttribute(gemm_mma,
        cudaFuncAttributeMaxDynamicSharedMemorySize, GEMM_SMEM);
    cudaFuncSetAttribute(scores_mma,
        cudaFuncAttributeMaxDynamicSharedMemorySize, SCORES_SMEM);
    cudaFuncSetAttribute(av_mma,
        cudaFuncAttributeMaxDynamicSharedMemorySize, AV_SMEM);

    const int n4 = (int)(XE / 4);
    tf32ize<<<(n4 + 255) / 256, 256>>>(q, q3, n4);
    tf32ize<<<(n4 + 255) / 256, 256>>>(k, k3, n4);
    tf32ize<<<(n4 + 255) / 256, 256>>>(v, v3, n4);

    const dim3 gT(32, 32);
    transpose1024<<<gT, dim3(32, 8)>>>(Wq,  wtq);
    transpose1024<<<gT, dim3(32, 8)>>>(Wfc, wtfc);

    const dim3 gG(Dc/128, (Bc*Sc)/128);        // (8, 64)
    gemm_mma<<<gG, 256, GEMM_SMEM>>>(q3, wtq, bq, nullptr, qh, 1, SCALEc);
    gemm_mma<<<gG, 256, GEMM_SMEM>>>(k3, wtq, bq, nullptr, kh, 1, 1.f);
    gemm_mma<<<gG, 256, GEMM_SMEM>>>(v3, wtq, bq, nullptr, vh, 1, 1.f);

    const dim3 gScores(Sc/128, Sc/128, BHc);   // (16, 16, 64)
    scores_mma<<<gScores, 256, SCORES_SMEM>>>(qh, kh, attn_region);

    rowinv_k<<<(BHc * Sc) / 256, 256>>>();

    const dim3 gAV(Sc/128, BHc);               // (16, 64)
    av_mma<<<gAV, 256, AV_SMEM>>>(attn_region, vh, ao);

    gemm_mma<<<gG, 256, GEMM_SMEM>>>(ao, wtfc, bfc, q, xb, 0, 1.f);

    ln_k<<<Bc*Sc, 256>>>(xb, gamma, beta, out);
}

// round 17
// speedup vs baseline: 1.0940x; 1.0940x over previous
#include <cuda_runtime.h>
#include <cuda_bf16.h>
#include <cstdint>
#include <cstddef>

// Problem constants
#define Bc  4
#define Sc  2048
#define Dc  1024
#define Hc  16
#define DKc 64
#define BHc (Bc*Hc)                     // 64
#define SCALEc 0.125f                   // DK^-0.5
#define EPSc 1e-6f

constexpr size_t XE = (size_t)Bc*Sc*Dc;       // 8,388,608
constexpr size_t AE = (size_t)Bc*Hc*Sc*Sc;    // 268,435,456

// ---------------- scratch (device globals: allocation-free) ----------------
__device__ float g_qkv3[3*XE];    // tf32-rounded q,k,v (slabs: q|k|v)
__device__ float g_hds[3*XE];     // projected heads qh|kh|vh, [B,H,S,DK] tf32
__device__ float g_ao[XE];        // attn@V [B,S,H*DK], tf32-pure
__device__ float g_x[XE];         // pre-LN activations (fp32)
__device__ float g_wt_q[Dc*Dc];   // Wq^T  [N,K] K-major, tf32-pure
__device__ float g_wt_fc[Dc*Dc];  // Wfc^T [N,K] K-major, tf32-pure
__device__ float g_psum[(size_t)BHc*16*Sc];   // partial row sums of exp
__device__ float g_rinv[(size_t)BHc*Sc];      // 1 / row sum
__device__ float g_attn_fb[AE];   // fallback if harness only wants x

// ============================================================================
// PTX helpers (all sm_80-or-earlier: legal on compute_103 target)
// ============================================================================
__device__ __forceinline__ float f2tf_f(float x) {
    uint32_t r;
    asm("cvt.rna.tf32.f32 %0, %1;" : "=r"(r) : "f"(x));
    return __uint_as_float(r);
}
__device__ __forceinline__ void mma8(float* d, const uint32_t* a, const uint32_t* b) {
    asm volatile(
        "mma.sync.aligned.m16n8k8.row.col.f32.tf32.tf32.f32 "
        "{%0,%1,%2,%3}, {%4,%5,%6,%7}, {%8,%9}, {%0,%1,%2,%3};"
        : "+f"(d[0]), "+f"(d[1]), "+f"(d[2]), "+f"(d[3])
        : "r"(a[0]), "r"(a[1]), "r"(a[2]), "r"(a[3]), "r"(b[0]), "r"(b[1]));
}
__device__ __forceinline__ uint32_t smem_u32p(const void* p) {
    uint32_t a;
    asm("{ .reg .u64 t; cvta.to.shared.u64 t, %1; cvt.u32.u64 %0, t; }"
        : "=r"(a) : "l"(p));
    return a;
}
#define CP_ASYNC16(dst_u32, src_gen) \
    asm volatile("cp.async.cg.shared.global [%0], [%1], 16;" \
                 :: "r"(dst_u32), "l"(src_gen) : "memory")
#define CP_COMMIT() asm volatile("cp.async.commit_group;" ::: "memory")
#define CP_WAIT(n)  asm volatile("cp.async.wait_group %0;" :: "n"(n) : "memory")
#define LDMX4(r0, r1, r2, r3, addr) \
    asm volatile("ldmatrix.sync.aligned.m8n8.x4.shared.b16 {%0,%1,%2,%3}, [%4];" \
                 : "=r"(r0), "=r"(r1), "=r"(r2), "=r"(r3) : "r"(addr))

// ============================================================================
// tf32-ize an array (float4)
// ============================================================================
__global__ __launch_bounds__(256) void tf32ize(
    const float* __restrict__ src, float* __restrict__ dst, int n4)
{
    const int idx = blockIdx.x * 256 + threadIdx.x;
    if (idx < n4) {
        float4 v = ((const float4*)src)[idx];
        v.x = f2tf_f(v.x); v.y = f2tf_f(v.y);
        v.z = f2tf_f(v.z); v.w = f2tf_f(v.w);
        ((float4*)dst)[idx] = v;
    }
}

// ============================================================================
// Transpose 1024x1024 + tf32-ize: Wt[n,k] = tf32(W[k,n])
// ============================================================================
__global__ __launch_bounds__(256) void transpose1024(
    const float* __restrict__ W, float* __restrict__ Wt)
{
    __shared__ float tile[32][33];
    const int x = blockIdx.x * 32 + threadIdx.x;
    const int y = blockIdx.y * 32 + threadIdx.y;
    #pragma unroll
    for (int j = 0; j < 32; j += 8)
        tile[threadIdx.y + j][threadIdx.x] = W[(size_t)(y + j) * Dc + x];
    __syncthreads();
    const int xo = blockIdx.y * 32 + threadIdx.x;
    const int yo = blockIdx.x * 32 + threadIdx.y;
    #pragma unroll
    for (int j = 0; j < 32; j += 8)
        Wt[(size_t)(yo + j) * Dc + xo] = f2tf_f(tile[threadIdx.x][threadIdx.y + j]);
}

// ============================================================================
// Dense GEMM, 512 threads (16 warps, 32x32 warp tiles), tf32 mma + ldmatrix
// + cp.async 3-stage. C[M,1024] = A[M,1024] @ Bt^T + bias (modes below).
// mode 0: C row-major, + resid, * outScale.
// mode 2: merged qkv projection: row slab (8192 rows each) -> qh|kh|vh head
//         layout; slab 0 (q) scaled by SCALEc. C = base of g_hds.
// ============================================================================
#define GSTRIDE 20
#define GSTAGE  2560                       // 128*20 floats
#define GEMM_SMEM (3 * GSTAGE * 2 * 4)     // 61440 B

__global__ __launch_bounds__(512, 2) void gemm_mma(
    const float* __restrict__ A, const float* __restrict__ Bt,
    const float* __restrict__ bias, const float* __restrict__ resid,
    float* __restrict__ C, int mode, float outScale)
{
    extern __shared__ float smf[];
    float* Asf = smf;                  // [3][128][20]
    float* Bsf = smf + 3 * GSTAGE;     // [3][128][20]
    const uint32_t asb = smem_u32p(Asf);
    const uint32_t bsb = smem_u32p(Bsf);

    const int tid  = threadIdx.x;
    const int lane = tid & 31;
    const int warp = tid >> 5;                 // 0..15
    const int g = lane >> 2, t = lane & 3;
    const int wm = (warp >> 2) * 32;           // 4 row groups
    const int wn = (warp & 3) * 32;            // 4 col groups
    const int mBase = blockIdx.y * 128;
    const int nBase = blockIdx.x * 128;

    const int i8 = lane & 7, qd = lane >> 3;
    const int a_off = (wm + i8 + (qd & 1) * 8) * GSTRIDE + (qd >> 1) * 4;
    const int b_off = (wn + i8 + (qd >> 1) * 8) * GSTRIDE + (qd & 1) * 4;

    const int lrow = tid >> 2;                 // 0..127
    const int lq = (tid & 3) * 4;              // 0,4,8,12
    const float* Ap = A  + (size_t)(mBase + lrow) * Dc + lq;
    const float* Bp = Bt + (size_t)(nBase + lrow) * Dc + lq;
    const uint32_t adst = (uint32_t)((lrow * GSTRIDE + lq) * 4);

    float acc[2][4][4];
    #pragma unroll
    for (int i = 0; i < 2; i++)
        #pragma unroll
        for (int j = 0; j < 4; j++)
            #pragma unroll
            for (int r = 0; r < 4; r++) acc[i][j][r] = 0.f;

    #pragma unroll
    for (int s = 0; s < 2; s++) {
        CP_ASYNC16(asb + s * (GSTAGE * 4) + adst, Ap + s * 16);
        CP_ASYNC16(bsb + s * (GSTAGE * 4) + adst, Bp + s * 16);
        CP_COMMIT();
    }

    #pragma unroll 1
    for (int kt = 0; kt < 64; kt++) {
        CP_WAIT(1);
        __syncthreads();
        const int cur = kt % 3;
        const uint32_t ab = asb + cur * (GSTAGE * 4);
        const uint32_t bb = bsb + cur * (GSTAGE * 4);
        #pragma unroll
        for (int ks = 0; ks < 2; ks++) {
            const int k0 = ks * 8;
            uint32_t afr[2][4], bfr[4][2];
            #pragma unroll
            for (int mt = 0; mt < 2; mt++)
                LDMX4(afr[mt][0], afr[mt][1], afr[mt][2], afr[mt][3],
                      ab + (uint32_t)((a_off + mt * 16 * GSTRIDE + k0) << 2));
            #pragma unroll
            for (int p = 0; p < 2; p++)
                LDMX4(bfr[2*p][0], bfr[2*p][1], bfr[2*p+1][0], bfr[2*p+1][1],
                      bb + (uint32_t)((b_off + p * 16 * GSTRIDE + k0) << 2));
            #pragma unroll
            for (int mt = 0; mt < 2; mt++)
                #pragma unroll
                for (int nt = 0; nt < 4; nt++)
                    mma8(acc[mt][nt], afr[mt], bfr[nt]);
        }
        if (kt + 2 < 64) {
            const int nst = (kt + 2) % 3;
            CP_ASYNC16(asb + nst * (GSTAGE * 4) + adst, Ap + (kt + 2) * 16);
            CP_ASYNC16(bsb + nst * (GSTAGE * 4) + adst, Bp + (kt + 2) * 16);
        }
        CP_COMMIT();
    }

    #pragma unroll
    for (int mt = 0; mt < 2; mt++) {
        #pragma unroll
        for (int nt = 0; nt < 4; nt++) {
            const int col = nBase + wn + nt * 8 + t * 2;
            #pragma unroll
            for (int h2 = 0; h2 < 2; h2++) {
                const int row = mBase + wm + mt * 16 + g + h2 * 8;
                float2 v;
                if (mode == 2) {
                    const int slab = row >> 13;        // 0=q,1=k,2=v
                    const int srow = row & 8191;
                    const float sc = (slab == 0) ? SCALEc : 1.f;
                    v.x = f2tf_f((acc[mt][nt][h2 * 2 + 0] + bias[col    ]) * sc);
                    v.y = f2tf_f((acc[mt][nt][h2 * 2 + 1] + bias[col + 1]) * sc);
                    const int b = srow >> 11, sI = srow & 2047;
                    const int h = col >> 6, dk = col & 63;
                    *(float2*)(C + (size_t)slab * XE
                               + (((size_t)(b * Hc + h)) * Sc + sI) * DKc + dk) = v;
                } else {
                    v.x = (acc[mt][nt][h2 * 2 + 0] + bias[col    ]) * outScale;
                    v.y = (acc[mt][nt][h2 * 2 + 1] + bias[col + 1]) * outScale;
                    if (resid) {
                        const float2 r = *(const float2*)(resid + (size_t)row * Dc + col);
                        v.x += r.x; v.y += r.y;
                    }
                    *(float2*)(C + (size_t)row * Dc + col) = v;
                }
            }
        }
    }
}

// ============================================================================
// Scores + exp + partial row sums, 512 threads (16 warps, 32x32 warp tiles).
// per (b,h) attn[r,c] = exp(qh[r]·kh[c]); partial row sums -> g_psum.
// ============================================================================
#define SCORES_SMEM (4 * GSTAGE * 2 * 4)   // 81920 B

__global__ __launch_bounds__(512, 2) void scores_mma(
    const float* __restrict__ qh, const float* __restrict__ kh,
    float* __restrict__ attn_out)
{
    float* attn = attn_out ? attn_out : g_attn_fb;
    extern __shared__ float smf[];
    float* Asf = smf;
    float* Bsf = smf + 4 * GSTAGE;
    const uint32_t asb = smem_u32p(Asf);
    const uint32_t bsb = smem_u32p(Bsf);

    const int tid  = threadIdx.x;
    const int lane = tid & 31;
    const int warp = tid >> 5;
    const int g = lane >> 2, t = lane & 3;
    const int wm = (warp >> 2) * 32;
    const int wn = (warp & 3) * 32;
    const int bh = blockIdx.z;
    const int mBase = blockIdx.y * 128;
    const int nBase = blockIdx.x * 128;

    const int i8 = lane & 7, qd = lane >> 3;
    const int a_off = (wm + i8 + (qd & 1) * 8) * GSTRIDE + (qd >> 1) * 4;
    const int b_off = (wn + i8 + (qd >> 1) * 8) * GSTRIDE + (qd & 1) * 4;

    const int lrow = tid >> 2;
    const int lq = (tid & 3) * 4;
    const float* Ap = qh + (size_t)bh * Sc * DKc + (size_t)(mBase + lrow) * DKc + lq;
    const float* Bp = kh + (size_t)bh * Sc * DKc + (size_t)(nBase + lrow) * DKc + lq;
    float* Cp = attn + (size_t)bh * Sc * Sc;
    const uint32_t adst = (uint32_t)((lrow * GSTRIDE + lq) * 4);

    #pragma unroll
    for (int s = 0; s < 4; s++) {
        CP_ASYNC16(asb + s * (GSTAGE * 4) + adst, Ap + s * 16);
        CP_ASYNC16(bsb + s * (GSTAGE * 4) + adst, Bp + s * 16);
    }
    CP_COMMIT();

    float acc[2][4][4];
    #pragma unroll
    for (int i = 0; i < 2; i++)
        #pragma unroll
        for (int j = 0; j < 4; j++)
            #pragma unroll
            for (int r = 0; r < 4; r++) acc[i][j][r] = 0.f;

    CP_WAIT(0);
    __syncthreads();

    #pragma unroll
    for (int kt = 0; kt < 4; kt++) {
        const uint32_t ab = asb + kt * (GSTAGE * 4);
        const uint32_t bb = bsb + kt * (GSTAGE * 4);
        #pragma unroll
        for (int ks = 0; ks < 2; ks++) {
            const int k0 = ks * 8;
            uint32_t afr[2][4], bfr[4][2];
            #pragma unroll
            for (int mt = 0; mt < 2; mt++)
                LDMX4(afr[mt][0], afr[mt][1], afr[mt][2], afr[mt][3],
                      ab + (uint32_t)((a_off + mt * 16 * GSTRIDE + k0) << 2));
            #pragma unroll
            for (int p = 0; p < 2; p++)
                LDMX4(bfr[2*p][0], bfr[2*p][1], bfr[2*p+1][0], bfr[2*p+1][1],
                      bb + (uint32_t)((b_off + p * 16 * GSTRIDE + k0) << 2));
            #pragma unroll
            for (int mt = 0; mt < 2; mt++)
                #pragma unroll
                for (int nt = 0; nt < 4; nt++)
                    mma8(acc[mt][nt], afr[mt], bfr[nt]);
        }
    }

    // epilogue: exp + store + per-row partial sums
    float rs[2][2];
    rs[0][0] = rs[0][1] = rs[1][0] = rs[1][1] = 0.f;

    #pragma unroll
    for (int mt = 0; mt < 2; mt++) {
        #pragma unroll
        for (int nt = 0; nt < 4; nt++) {
            const int col = nBase + wn + nt * 8 + t * 2;
            #pragma unroll
            for (int h2 = 0; h2 < 2; h2++) {
                const int row = mBase + wm + mt * 16 + g + h2 * 8;
                float2 v;
                v.x = __expf(acc[mt][nt][h2 * 2 + 0]);
                v.y = __expf(acc[mt][nt][h2 * 2 + 1]);
                rs[mt][h2] += v.x + v.y;
                *(float2*)(Cp + (size_t)row * Sc + col) = v;
            }
        }
    }

    __syncthreads();          // tile reads done; reuse Asf as psum buffer
    float* psum = Asf;        // [4 wx][128 rows]
    #pragma unroll
    for (int mt = 0; mt < 2; mt++) {
        #pragma unroll
        for (int h2 = 0; h2 < 2; h2++) {
            float s = rs[mt][h2];
            s += __shfl_xor_sync(0xFFFFFFFFu, s, 1);
            s += __shfl_xor_sync(0xFFFFFFFFu, s, 2);
            if (t == 0)
                psum[(warp & 3) * 128 + wm + mt * 16 + h2 * 8 + g] = s;
        }
    }
    __syncthreads();
    if (tid < 128) {
        const float tot = psum[tid] + psum[128 + tid] + psum[256 + tid] + psum[384 + tid];
        g_psum[(((size_t)bh * 16 + blockIdx.x) << 11) + mBase + tid] = tot;
    }
}

// ============================================================================
// Row inverse sums: g_rinv[bh*S + row] = 1 / sum_j g_psum[bh][j][row]
// ============================================================================
__global__ __launch_bounds__(256) void rowinv_k()
{
    const int r = blockIdx.x * 256 + threadIdx.x;
    const int bh = r >> 11, row = r & 2047;
    float s = 0.f;
    #pragma unroll
    for (int j = 0; j < 16; j++)
        s += g_psum[(((size_t)bh * 16 + j) << 11) + row];
    g_rinv[r] = 1.f / s;
}

// ============================================================================
// attn @ V (unnormalized exp in, scaling fused), 256 threads, 4-stage.
// ao = diag(rinv) * (E @ V); normalized attn written back in-place.
// ============================================================================
#define VSTRIDE 72
#define VSTAGE  (16 * VSTRIDE)
#define AV_SMEM ((4 * GSTAGE + 4 * VSTAGE + 128) * 4)   // 59904 B

__global__ __launch_bounds__(256) void av_mma(
    float* __restrict__ attn_out, const float* __restrict__ vh,
    float* __restrict__ ao)
{
    float* attn = attn_out ? attn_out : g_attn_fb;
    extern __shared__ float smf[];
    float* Asf = smf;                    // [4][128][20]
    float* Vsf = smf + 4 * GSTAGE;       // [4][16][72]
    float* sinv = smf + 4 * GSTAGE + 4 * VSTAGE;   // [128]
    const uint32_t asb = smem_u32p(Asf);
    const uint32_t vsb = smem_u32p(Vsf);

    const int tid  = threadIdx.x;
    const int lane = tid & 31;
    const int warp = tid >> 5;
    const int g = lane >> 2, t = lane & 3;
    const int wm = (warp >> 1) * 32;
    const int wn = (warp & 1) * 32;
    const int bh = blockIdx.y;
    const int mBase = blockIdx.x * 128;

    const int i8 = lane & 7, qd = lane >> 3;
    const int a_off = (wm + i8 + (qd & 1) * 8) * GSTRIDE + (qd >> 1) * 4;

    const int lrow = tid >> 1;
    const int lhalf = (tid & 1) * 8;
    const int vrow = tid >> 4;
    const int vcol = (tid & 15) * 4;
    float* Ag = attn + (size_t)bh * Sc * Sc + (size_t)(mBase + lrow) * Sc + lhalf;
    const float* Vp = vh + (size_t)bh * Sc * DKc;
    const uint32_t adst = (uint32_t)((lrow * GSTRIDE + lhalf) * 4);
    const uint32_t vdst = (uint32_t)((vrow * VSTRIDE + vcol) * 4);

    if (tid < 128)
        sinv[tid] = g_rinv[(size_t)bh * Sc + mBase + tid];

    float acc[2][4][4];
    #pragma unroll
    for (int i = 0; i < 2; i++)
        #pragma unroll
        for (int j = 0; j < 4; j++)
            #pragma unroll
            for (int r = 0; r < 4; r++) acc[i][j][r] = 0.f;

    #pragma unroll
    for (int s = 0; s < 3; s++) {
        const uint32_t ad = asb + s * (GSTAGE * 4) + adst;
        CP_ASYNC16(ad,      Ag + s * 16);
        CP_ASYNC16(ad + 16, Ag + s * 16 + 4);
        CP_ASYNC16(vsb + s * (VSTAGE * 4) + vdst,
                   Vp + (size_t)(s * 16 + vrow) * DKc + vcol);
        CP_COMMIT();
    }

    float wrow_inv = 0.f;

    #pragma unroll 1
    for (int kt = 0; kt < 128; kt++) {
        CP_WAIT(2);
        __syncthreads();
        if (kt == 0) wrow_inv = sinv[lrow];
        const int cur = kt & 3;
        const uint32_t ab = asb + cur * (GSTAGE * 4);
        const float* Af = Asf + cur * GSTAGE;
        const float* Vf = Vsf + cur * VSTAGE;

        {
            float4 w0 = *(const float4*)(Af + lrow * GSTRIDE + lhalf);
            float4 w1 = *(const float4*)(Af + lrow * GSTRIDE + lhalf + 4);
            w0.x *= wrow_inv; w0.y *= wrow_inv; w0.z *= wrow_inv; w0.w *= wrow_inv;
            w1.x *= wrow_inv; w1.y *= wrow_inv; w1.z *= wrow_inv; w1.w *= wrow_inv;
            *(float4*)(Ag + kt * 16)     = w0;
            *(float4*)(Ag + kt * 16 + 4) = w1;
        }

        #pragma unroll
        for (int ks = 0; ks < 2; ks++) {
            const int k0 = ks * 8;
            uint32_t afr[2][4], bfr[4][2];
            #pragma unroll
            for (int mt = 0; mt < 2; mt++)
                LDMX4(afr[mt][0], afr[mt][1], afr[mt][2], afr[mt][3],
                      ab + (uint32_t)((a_off + mt * 16 * GSTRIDE + k0) << 2));
            #pragma unroll
            for (int nt = 0; nt < 4; nt++) {
                const int c = wn + nt * 8 + g;
                bfr[nt][0] = __float_as_uint(Vf[(k0 + t    ) * VSTRIDE + c]);
                bfr[nt][1] = __float_as_uint(Vf[(k0 + t + 4) * VSTRIDE + c]);
            }
            #pragma unroll
            for (int mt = 0; mt < 2; mt++)
                #pragma unroll
                for (int nt = 0; nt < 4; nt++)
                    mma8(acc[mt][nt], afr[mt], bfr[nt]);
        }
        if (kt + 3 < 128) {
            const int nst = (kt + 3) & 3;
            const uint32_t ad = asb + nst * (GSTAGE * 4) + adst;
            CP_ASYNC16(ad,      Ag + (kt + 3) * 16);
            CP_ASYNC16(ad + 16, Ag + (kt + 3) * 16 + 4);
            CP_ASYNC16(vsb + nst * (VSTAGE * 4) + vdst,
                       Vp + (size_t)((kt + 3) * 16 + vrow) * DKc + vcol);
        }
        CP_COMMIT();
    }

    const int b = bh >> 4, h = bh & 15;
    #pragma unroll
    for (int mt = 0; mt < 2; mt++) {
        #pragma unroll
        for (int nt = 0; nt < 4; nt++) {
            const int col = wn + nt * 8 + t * 2;
            #pragma unroll
            for (int h2 = 0; h2 < 2; h2++) {
                const int lr = wm + mt * 16 + g + h2 * 8;
                const float inv = sinv[lr];
                const int row = mBase + lr;
                float2 v = { f2tf_f(acc[mt][nt][h2 * 2 + 0] * inv),
                             f2tf_f(acc[mt][nt][h2 * 2 + 1] * inv) };
                *(float2*)(ao + ((size_t)(b * Sc + row)) * Dc + h * DKc + col) = v;
            }
        }
    }
}

// ============================================================================
// LayerNorm over D=1024.
// ============================================================================
__global__ __launch_bounds__(256) void ln_k(
    const float* __restrict__ x, const float* __restrict__ gamma,
    const float* __restrict__ beta, float* __restrict__ out)
{
    __shared__ float r1[256];
    __shared__ float r2[256];
    const int t = threadIdx.x;
    const float* p = x + (size_t)blockIdx.x * Dc;

    float v[4];
    float s = 0.f, sq = 0.f;
    #pragma unroll
    for (int i = 0; i < 4; i++) {
        v[i] = p[t + i*256];
        s += v[i]; sq += v[i]*v[i];
    }
    r1[t] = s; r2[t] = sq; __syncthreads();
    for (int w = 128; w > 0; w >>= 1) {
        if (t < w) { r1[t] += r1[t+w]; r2[t] += r2[t+w]; }
        __syncthreads();
    }
    const float mu  = r1[0] * (1.f/Dc);
    const float var = r2[0] * (1.f/Dc) - mu*mu;
    const float inv = rsqrtf(var + EPSc);
    float* o = out + (size_t)blockIdx.x * Dc;
    #pragma unroll
    for (int i = 0; i < 4; i++) {
        const int c = t + i*256;
        o[c] = (v[i] - mu) * inv * gamma[c] + beta[c];
    }
}

// ============================================================================
// Launch
// ============================================================================
extern "C" void kernel_launch(void* const* d_in, const int* in_sizes, int n_in,
                              void* d_out, int out_size)
{
    const float* q     = (const float*)d_in[0];
    const float* k     = (const float*)d_in[1];
    const float* v     = (const float*)d_in[2];
    const float* Wq    = (const float*)d_in[3];
    const float* bq    = (const float*)d_in[4];
    const float* Wfc   = (const float*)d_in[5];
    const float* bfc   = (const float*)d_in[6];
    const float* gamma = (const float*)d_in[7];
    const float* beta  = (const float*)d_in[8];

    float* out = (float*)d_out;
    float* attn_region = ((size_t)out_size >= XE + AE) ? (out + XE) : nullptr;

    float *qkv3, *hds, *ao, *xb, *wtq, *wtfc;
    cudaGetSymbolAddress((void**)&qkv3, g_qkv3);
    cudaGetSymbolAddress((void**)&hds,  g_hds);
    cudaGetSymbolAddress((void**)&ao,   g_ao);
    cudaGetSymbolAddress((void**)&xb,   g_x);
    cudaGetSymbolAddress((void**)&wtq,  g_wt_q);
    cudaGetSymbolAddress((void**)&wtfc, g_wt_fc);

    cudaFuncSetAttribute(gemm_mma,
        cudaFuncAttributeMaxDynamicSharedMemorySize, GEMM_SMEM);
    cudaFuncSetAttribute(scores_mma,
        cudaFuncAttributeMaxDynamicSharedMemorySize, SCORES_SMEM);
    cudaFuncSetAttribute(av_mma,
        cudaFuncAttributeMaxDynamicSharedMemorySize, AV_SMEM);

    const int n4 = (int)(XE / 4);
    tf32ize<<<(n4 + 255) / 256, 256>>>(q, qkv3,          n4);
    tf32ize<<<(n4 + 255) / 256, 256>>>(k, qkv3 + XE,     n4);
    tf32ize<<<(n4 + 255) / 256, 256>>>(v, qkv3 + 2 * XE, n4);

    const dim3 gT(32, 32);
    transpose1024<<<gT, dim3(32, 8)>>>(Wq,  wtq);
    transpose1024<<<gT, dim3(32, 8)>>>(Wfc, wtfc);

    // Merged q/k/v projection: one launch, M = 24576
    gemm_mma<<<dim3(Dc/128, (3*Bc*Sc)/128), 512, GEMM_SMEM>>>(
        qkv3, wtq, bq, nullptr, hds, 2, 1.f);

    const float* qh = hds;
    const float* kh = hds + XE;
    const float* vh = hds + 2 * XE;

    const dim3 gScores(Sc/128, Sc/128, BHc);   // (16, 16, 64)
    scores_mma<<<gScores, 512, SCORES_SMEM>>>(qh, kh, attn_region);

    rowinv_k<<<(BHc * Sc) / 256, 256>>>();

    const dim3 gAV(Sc/128, BHc);               // (16, 64)
    av_mma<<<gAV, 256, AV_SMEM>>>(attn_region, vh, ao);

    gemm_mma<<<dim3(Dc/128, (Bc*Sc)/128), 512, GEMM_SMEM>>>(
        ao, wtfc, bfc, q, xb, 0, 1.f);

    ln_k<<<Bc*Sc, 256>>>(xb, gamma, beta, out);
}